// round 6
// baseline (speedup 1.0000x reference)
#include <cuda_runtime.h>

#define NA   25
#define NHW  1444
#define NV   361          // NHW / 4 (float4 units per plane)
#define BMAX 512

__constant__ float c_bw[5] = {1.3221f, 3.19275f, 5.05587f, 9.47112f, 11.2364f};
__constant__ float c_bh[5] = {1.73145f, 4.00944f, 8.09892f, 4.84053f, 10.0071f};
__constant__ float c_sc[5] = {0.5f, 0.75f, 1.0f, 1.25f, 1.5f};

struct BP {
    float gl, gr, gt, gb;     // gt box edges
    float gw, gh, garea;
    float txt, tyt, twt, tht; // coord targets at the special cell
    int   sidx, best;
};

__device__ __align__(16) float g_part[BMAX * NA];
__device__ unsigned g_done = 0;

__device__ __forceinline__ float tanhapx(float x) {
    float t;
    asm("tanh.approx.f32 %0, %1;" : "=f"(t) : "f"(x));
    return t;
}

// release-scoped add: orders the prior g_part store at L2 WITHOUT the
// gpu-scope fence's CCTL.IVALL L1-flush (the R5 regression mechanism)
__device__ __forceinline__ unsigned atomic_inc_release(unsigned* p) {
    unsigned old;
    asm volatile("atom.release.gpu.add.u32 %0, [%1], %2;"
                 : "=r"(old) : "l"(p), "r"(1u) : "memory");
    return old;
}

struct CO { float dense, inter, uni, sx, sy, pc; };

// Per-cell evaluation. hw/hh are HALF widths (0.5*anchor folded into lhw/lhh).
__device__ __forceinline__ CO cell_eval(
    float tx, float ty, float tw, float th, float tc,
    float cxw, float cyh, float lhw, float lhh,
    float gl, float gr, float gt, float gb,
    float gw, float gh, float garea)
{
    const float L2E = 1.4426950408889634f;
    float tX = tanhapx(0.5f * tx);
    float tY = tanhapx(0.5f * ty);
    float tC = tanhapx(0.5f * tc);
    float bx = fmaf(tX, 0.5f, cxw);            // sigmoid(tx) + w
    float by = fmaf(tY, 0.5f, cyh);
    float hw = exp2f(fmaf(tw, L2E, lhw));      // 0.5 * aw * exp(tw)
    float hh = exp2f(fmaf(th, L2E, lhh));
    float mx = fminf(bx - hw, gl);
    float Mx = fmaxf(bx + hw, gr);
    float my = fminf(by - hh, gt);
    float My = fmaxf(by + hh, gb);
    float cw = fmaf(hw, 2.0f, gw) - (Mx - mx);
    float ch = fmaf(hh, 2.0f, gh) - (My - my);
    float inter = (cw > 0.0f && ch > 0.0f) ? cw * ch : 0.0f;
    float uni   = fmaf(hw * hh, 4.0f, garea) - inter;
    bool noobj  = fmaf(uni, -0.6f, inter) <= 0.0f;   // !(iou > 0.6)
    float pc = fmaf(tC, 0.5f, 0.5f);
    float confsq = noobj ? pc * pc : 0.0f;
    float s1 = fmaf(tX, tX, tY * tY);          // (2*dx)^2 + (2*dy)^2
    float s2 = fmaf(tw, tw, th * th);          // dw^2 + dh^2 (targets 0)
    CO o;
    o.dense = fmaf(s1, 0.125f, fmaf(s2, 0.5f, 0.5f * confsq));
    o.inter = inter; o.uni = uni;
    o.sx = fmaf(tX, 0.5f, 0.5f);
    o.sy = fmaf(tY, 0.5f, 0.5f);
    o.pc = pc;
    return o;
}

__global__ void __launch_bounds__(128) main_kernel(
    const float* __restrict__ pred, const float* __restrict__ tgt,
    float* __restrict__ out, int total)
{
    const int a = blockIdx.x;
    const int b = blockIdx.y;

    __shared__ BP sbp;
    __shared__ float ws[4];
    __shared__ bool isLast;

    if (threadIdx.x == 0) {
        float gx = tgt[4 * b + 0] * 38.0f;
        float gy = tgt[4 * b + 1] * 38.0f;
        float gw = tgt[4 * b + 2] * 38.0f;
        float gh = tgt[4 * b + 3] * 38.0f;
        int gi = (int)gx;
        int gj = (int)gy;
        float garea = gw * gh;

        // division-free argmax over anchor IoUs (first max wins)
        int best = 0;
        float binter = 0.0f, buni = 1.0f;
#pragma unroll
        for (int ai = 0; ai < NA; ai++) {
            float aw = c_bw[ai % 5] * c_sc[ai / 5];
            float ah = c_bh[ai % 5] * c_sc[ai / 5];
            float in_ = fminf(aw, gw) * fminf(ah, gh);
            float un  = aw * ah + garea - in_;
            if (ai == 0 || in_ * buni > binter * un) {
                binter = in_; buni = un; best = ai;
            }
        }
        float baw = c_bw[best % 5] * c_sc[best / 5];
        float bah = c_bh[best % 5] * c_sc[best / 5];

        BP bp;
        bp.gl = gx - 0.5f * gw;  bp.gr = gx + 0.5f * gw;
        bp.gt = gy - 0.5f * gh;  bp.gb = gy + 0.5f * gh;
        bp.gw = gw; bp.gh = gh; bp.garea = garea;
        bp.txt = gx - (float)gi;
        bp.tyt = gy - (float)gj;
        bp.twt = logf(gw / baw);
        bp.tht = logf(gh / bah);
        bp.sidx = gj * 38 + gi;
        bp.best = best;
        sbp = bp;
    }
    __syncthreads();
    const BP bp = sbp;

    int am = a - (a / 5) * 5;
    float aw = c_bw[am] * c_sc[a / 5];
    float ah = c_bh[am] * c_sc[a / 5];
    float lhw = __log2f(0.5f * aw);
    float lhh = __log2f(0.5f * ah);

    const float4* __restrict__ p4 =
        (const float4*)(pred + (size_t)(b * NA + a) * 5 * NHW);

    float acc = 0.0f;
    for (int v = threadIdx.x; v < NV; v += 128) {
        float4 X = p4[v];
        float4 Y = p4[v + NV];
        float4 W = p4[v + 2 * NV];
        float4 H = p4[v + 3 * NV];
        float4 C = p4[v + 4 * NV];
        float xa[4] = {X.x, X.y, X.z, X.w};
        float ya[4] = {Y.x, Y.y, Y.z, Y.w};
        float wa[4] = {W.x, W.y, W.z, W.w};
        float ha[4] = {H.x, H.y, H.z, H.w};
        float ca[4] = {C.x, C.y, C.z, C.w};
        int base = 4 * v;
#pragma unroll
        for (int k = 0; k < 4; k++) {
            int idx = base + k;
            int hh_ = (idx * 1725) >> 16;      // idx / 38
            int ww_ = idx - hh_ * 38;
            CO o = cell_eval(xa[k], ya[k], wa[k], ha[k], ca[k],
                             (float)ww_ + 0.5f, (float)hh_ + 0.5f,
                             lhw, lhh,
                             bp.gl, bp.gr, bp.gt, bp.gb,
                             bp.gw, bp.gh, bp.garea);
            acc += o.dense;
        }
    }

    // special-cell correction: one block per batch owns it
    if (threadIdx.x == 0 && a == bp.best) {
        int idx = bp.sidx;
        const float* p = pred + (size_t)(b * NA + a) * 5 * NHW;
        float tx = __ldg(p + idx);
        float ty = __ldg(p + idx + NHW);
        float tw = __ldg(p + idx + 2 * NHW);
        float th = __ldg(p + idx + 3 * NHW);
        float tc = __ldg(p + idx + 4 * NHW);
        int hh_ = (idx * 1725) >> 16;
        int ww_ = idx - hh_ * 38;
        CO o = cell_eval(tx, ty, tw, th, tc,
                         (float)ww_ + 0.5f, (float)hh_ + 0.5f,
                         lhw, lhh,
                         bp.gl, bp.gr, bp.gt, bp.gb,
                         bp.gw, bp.gh, bp.garea);
        float dx = o.sx - bp.txt;
        float dy = o.sy - bp.tyt;
        float dw = tw - bp.twt;
        float dh = th - bp.tht;
        float tconf = o.inter / o.uni;
        float dc = o.pc - tconf;
        float truec = 0.5f * (dx * dx + dy * dy + dw * dw + dh * dh)
                    + 2.5f * (dc * dc);               // OBJECT_SCALE/2
        acc += truec - o.dense;
    }

    // deterministic block reduction (4 warps)
#pragma unroll
    for (int off = 16; off > 0; off >>= 1)
        acc += __shfl_down_sync(0xffffffffu, acc, off);
    if ((threadIdx.x & 31) == 0) ws[threadIdx.x >> 5] = acc;
    __syncthreads();
    if (threadIdx.x == 0) {
        g_part[b * NA + a] = (ws[0] + ws[1]) + (ws[2] + ws[3]);
        // release-inc: NO per-block L1 flush (vs __threadfence in R5)
        unsigned t = atomic_inc_release(&g_done);
        isLast = (t == (unsigned)(total - 1));
    }
    __syncthreads();

    // last block performs the (deterministic-order) final reduction
    if (isLast) {
        if (threadIdx.x == 0) {
            g_done = 0;          // reset for next graph replay
            __threadfence();     // single acquire-side fence, once per grid
        }
        __syncthreads();
        __shared__ double sh[128];
        const float4* __restrict__ pp = (const float4*)g_part;
        int n4 = total >> 2;
        double s = 0.0;
        for (int i = threadIdx.x; i < n4; i += 128) {
            float4 v = __ldcg(pp + i);   // L2 reads = coherence point
            s += ((double)v.x + (double)v.y) + ((double)v.z + (double)v.w);
        }
        sh[threadIdx.x] = s;
        __syncthreads();
#pragma unroll
        for (int off = 64; off > 0; off >>= 1) {
            if (threadIdx.x < off) sh[threadIdx.x] += sh[threadIdx.x + off];
            __syncthreads();
        }
        if (threadIdx.x == 0) out[0] = (float)sh[0];
    }
}

extern "C" void kernel_launch(void* const* d_in, const int* in_sizes, int n_in,
                              void* d_out, int out_size) {
    const float* pred = (const float*)d_in[0];
    const float* tgt  = (const float*)d_in[1];
    int B = in_sizes[1] / 4;
    if (B > BMAX) B = BMAX;

    dim3 grid(NA, B);
    main_kernel<<<grid, 128>>>(pred, tgt, (float*)d_out, B * NA);
}

// round 7
// speedup vs baseline: 1.0826x; 1.0826x over previous
#include <cuda_runtime.h>

#define NA   25
#define NHW  1444
#define NV   361          // NHW / 4 (float4 units per plane)
#define BMAX 512

__constant__ float c_bw[5] = {1.3221f, 3.19275f, 5.05587f, 9.47112f, 11.2364f};
__constant__ float c_bh[5] = {1.73145f, 4.00944f, 8.09892f, 4.84053f, 10.0071f};
__constant__ float c_sc[5] = {0.5f, 0.75f, 1.0f, 1.25f, 1.5f};

struct BP {
    float gl, gr, gt, gb;     // gt box edges
    float gw, gh, garea;
    float txt, tyt, twt, tht; // coord targets at the special cell
    int   sidx, best;
};

__device__ __align__(16) float g_part[BMAX * NA];
__device__ unsigned g_done = 0;

__device__ __forceinline__ float tanhapx(float x) {
    float t;
    asm("tanh.approx.f32 %0, %1;" : "=f"(t) : "f"(x));
    return t;
}

__device__ __forceinline__ unsigned atomic_inc_release(unsigned* p) {
    unsigned old;
    asm volatile("atom.release.gpu.add.u32 %0, [%1], %2;"
                 : "=r"(old) : "l"(p), "r"(1u) : "memory");
    return old;
}

struct CO { float dense, inter, uni, sx, sy, pc; };

// Per-cell evaluation. hw/hh are HALF widths (0.5*anchor folded into lhw/lhh).
__device__ __forceinline__ CO cell_eval(
    float tx, float ty, float tw, float th, float tc,
    float cxw, float cyh, float lhw, float lhh,
    float gl, float gr, float gt, float gb,
    float gw, float gh, float garea)
{
    const float L2E = 1.4426950408889634f;
    float tX = tanhapx(0.5f * tx);
    float tY = tanhapx(0.5f * ty);
    float tC = tanhapx(0.5f * tc);
    float bx = fmaf(tX, 0.5f, cxw);            // sigmoid(tx) + w
    float by = fmaf(tY, 0.5f, cyh);
    float hw = exp2f(fmaf(tw, L2E, lhw));      // 0.5 * aw * exp(tw)
    float hh = exp2f(fmaf(th, L2E, lhh));
    float mx = fminf(bx - hw, gl);
    float Mx = fmaxf(bx + hw, gr);
    float my = fminf(by - hh, gt);
    float My = fmaxf(by + hh, gb);
    float cw = fmaf(hw, 2.0f, gw) - (Mx - mx);
    float ch = fmaf(hh, 2.0f, gh) - (My - my);
    float inter = (cw > 0.0f && ch > 0.0f) ? cw * ch : 0.0f;
    float uni   = fmaf(hw * hh, 4.0f, garea) - inter;
    bool noobj  = fmaf(uni, -0.6f, inter) <= 0.0f;   // !(iou > 0.6)
    float pc = fmaf(tC, 0.5f, 0.5f);
    float confsq = noobj ? pc * pc : 0.0f;
    float s1 = fmaf(tX, tX, tY * tY);          // (2*dx)^2 + (2*dy)^2
    float s2 = fmaf(tw, tw, th * th);          // dw^2 + dh^2 (targets 0)
    CO o;
    o.dense = fmaf(s1, 0.125f, fmaf(s2, 0.5f, 0.5f * confsq));
    o.inter = inter; o.uni = uni;
    o.sx = fmaf(tX, 0.5f, 0.5f);
    o.sy = fmaf(tY, 0.5f, 0.5f);
    o.pc = pc;
    return o;
}

// process one float4 group (4 cells starting at cell index base=4*v)
__device__ __forceinline__ float group_eval(
    const float4& X, const float4& Y, const float4& W,
    const float4& H, const float4& C, int base,
    float lhw, float lhh, const BP& bp)
{
    float xa[4] = {X.x, X.y, X.z, X.w};
    float ya[4] = {Y.x, Y.y, Y.z, Y.w};
    float wa[4] = {W.x, W.y, W.z, W.w};
    float ha[4] = {H.x, H.y, H.z, H.w};
    float ca[4] = {C.x, C.y, C.z, C.w};
    float s = 0.0f;
#pragma unroll
    for (int k = 0; k < 4; k++) {
        int idx = base + k;
        int hh_ = (idx * 1725) >> 16;      // idx / 38
        int ww_ = idx - hh_ * 38;
        CO o = cell_eval(xa[k], ya[k], wa[k], ha[k], ca[k],
                         (float)ww_ + 0.5f, (float)hh_ + 0.5f,
                         lhw, lhh,
                         bp.gl, bp.gr, bp.gt, bp.gb,
                         bp.gw, bp.gh, bp.garea);
        s += o.dense;
    }
    return s;
}

__global__ void __launch_bounds__(128) main_kernel(
    const float* __restrict__ pred, const float* __restrict__ tgt,
    float* __restrict__ out, int total)
{
    const int a = blockIdx.x;
    const int b = blockIdx.y;

    __shared__ BP sbp;
    __shared__ float ws[4];
    __shared__ bool isLast;

    const float4* __restrict__ p4 =
        (const float4*)(pred + (size_t)(b * NA + a) * 5 * NHW);
    const int v = threadIdx.x;

    // ---- issue 10 independent LDG.128 up front (MLP_p1 = 10); these do NOT
    // depend on the prologue, so they hide its latency under the barrier ----
    float4 X0 = p4[v];
    float4 Y0 = p4[v + NV];
    float4 W0 = p4[v + 2 * NV];
    float4 H0 = p4[v + 3 * NV];
    float4 C0 = p4[v + 4 * NV];
    float4 X1 = p4[v + 128];
    float4 Y1 = p4[v + 128 + NV];
    float4 W1 = p4[v + 128 + 2 * NV];
    float4 H1 = p4[v + 128 + 3 * NV];
    float4 C1 = p4[v + 128 + 4 * NV];

    if (threadIdx.x == 0) {
        float gx = tgt[4 * b + 0] * 38.0f;
        float gy = tgt[4 * b + 1] * 38.0f;
        float gw = tgt[4 * b + 2] * 38.0f;
        float gh = tgt[4 * b + 3] * 38.0f;
        int gi = (int)gx;
        int gj = (int)gy;
        float garea = gw * gh;

        // division-free argmax over anchor IoUs (first max wins)
        int best = 0;
        float binter = 0.0f, buni = 1.0f;
#pragma unroll
        for (int ai = 0; ai < NA; ai++) {
            float aw = c_bw[ai % 5] * c_sc[ai / 5];
            float ah = c_bh[ai % 5] * c_sc[ai / 5];
            float in_ = fminf(aw, gw) * fminf(ah, gh);
            float un  = aw * ah + garea - in_;
            if (ai == 0 || in_ * buni > binter * un) {
                binter = in_; buni = un; best = ai;
            }
        }
        float baw = c_bw[best % 5] * c_sc[best / 5];
        float bah = c_bh[best % 5] * c_sc[best / 5];

        BP bp;
        bp.gl = gx - 0.5f * gw;  bp.gr = gx + 0.5f * gw;
        bp.gt = gy - 0.5f * gh;  bp.gb = gy + 0.5f * gh;
        bp.gw = gw; bp.gh = gh; bp.garea = garea;
        bp.txt = gx - (float)gi;
        bp.tyt = gy - (float)gj;
        bp.twt = logf(gw / baw);
        bp.tht = logf(gh / bah);
        bp.sidx = gj * 38 + gi;
        bp.best = best;
        sbp = bp;
    }
    __syncthreads();
    const BP bp = sbp;

    int am = a - (a / 5) * 5;
    float aw = c_bw[am] * c_sc[a / 5];
    float ah = c_bh[am] * c_sc[a / 5];
    float lhw = __log2f(0.5f * aw);
    float lhh = __log2f(0.5f * ah);

    // same per-thread accumulation order as before: v, v+128, v+256
    float acc = group_eval(X0, Y0, W0, H0, C0, 4 * v, lhw, lhh, bp);
    acc      += group_eval(X1, Y1, W1, H1, C1, 4 * (v + 128), lhw, lhh, bp);

    if (v + 256 < NV) {
        float4 X2 = p4[v + 256];
        float4 Y2 = p4[v + 256 + NV];
        float4 W2 = p4[v + 256 + 2 * NV];
        float4 H2 = p4[v + 256 + 3 * NV];
        float4 C2 = p4[v + 256 + 4 * NV];
        acc += group_eval(X2, Y2, W2, H2, C2, 4 * (v + 256), lhw, lhh, bp);
    }

    // special-cell correction: one block per batch owns it
    if (threadIdx.x == 0 && a == bp.best) {
        int idx = bp.sidx;
        const float* p = pred + (size_t)(b * NA + a) * 5 * NHW;
        float tx = __ldg(p + idx);
        float ty = __ldg(p + idx + NHW);
        float tw = __ldg(p + idx + 2 * NHW);
        float th = __ldg(p + idx + 3 * NHW);
        float tc = __ldg(p + idx + 4 * NHW);
        int hh_ = (idx * 1725) >> 16;
        int ww_ = idx - hh_ * 38;
        CO o = cell_eval(tx, ty, tw, th, tc,
                         (float)ww_ + 0.5f, (float)hh_ + 0.5f,
                         lhw, lhh,
                         bp.gl, bp.gr, bp.gt, bp.gb,
                         bp.gw, bp.gh, bp.garea);
        float dx = o.sx - bp.txt;
        float dy = o.sy - bp.tyt;
        float dw = tw - bp.twt;
        float dh = th - bp.tht;
        float tconf = o.inter / o.uni;
        float dc = o.pc - tconf;
        float truec = 0.5f * (dx * dx + dy * dy + dw * dw + dh * dh)
                    + 2.5f * (dc * dc);               // OBJECT_SCALE/2
        acc += truec - o.dense;
    }

    // deterministic block reduction (4 warps)
#pragma unroll
    for (int off = 16; off > 0; off >>= 1)
        acc += __shfl_down_sync(0xffffffffu, acc, off);
    if ((threadIdx.x & 31) == 0) ws[threadIdx.x >> 5] = acc;
    __syncthreads();
    if (threadIdx.x == 0) {
        g_part[b * NA + a] = (ws[0] + ws[1]) + (ws[2] + ws[3]);
        unsigned t = atomic_inc_release(&g_done);
        isLast = (t == (unsigned)(total - 1));
    }
    __syncthreads();

    // last block performs the (deterministic-order) final reduction
    if (isLast) {
        if (threadIdx.x == 0) {
            g_done = 0;          // reset for next graph replay
            __threadfence();     // single acquire-side fence, once per grid
        }
        __syncthreads();
        __shared__ double sh[128];
        const float4* __restrict__ pp = (const float4*)g_part;
        int n4 = total >> 2;
        double s = 0.0;
        for (int i = threadIdx.x; i < n4; i += 128) {
            float4 vv = __ldcg(pp + i);   // L2 reads = coherence point
            s += ((double)vv.x + (double)vv.y) + ((double)vv.z + (double)vv.w);
        }
        sh[threadIdx.x] = s;
        __syncthreads();
#pragma unroll
        for (int off = 64; off > 0; off >>= 1) {
            if (threadIdx.x < off) sh[threadIdx.x] += sh[threadIdx.x + off];
            __syncthreads();
        }
        if (threadIdx.x == 0) out[0] = (float)sh[0];
    }
}

extern "C" void kernel_launch(void* const* d_in, const int* in_sizes, int n_in,
                              void* d_out, int out_size) {
    const float* pred = (const float*)d_in[0];
    const float* tgt  = (const float*)d_in[1];
    int B = in_sizes[1] / 4;
    if (B > BMAX) B = BMAX;

    dim3 grid(NA, B);
    main_kernel<<<grid, 128>>>(pred, tgt, (float*)d_out, B * NA);
}